// round 1
// baseline (speedup 1.0000x reference)
#include <cuda_runtime.h>
#include <math.h>

namespace {
constexpr int kB = 8;
constexpr int kN = 4096;
constexpr int kD = 512;
constexpr int kL = 64;
constexpr float kInvTemp = 0.044194173824159216f; // 1/sqrt(512)
}

// ---------------- scratch (device globals; no allocation allowed) ----------
__device__ int   g_mask_kind;          // 0=uint8, 1=int32, 2=float32
__device__ int   g_order[kB * kN];     // sorted-valid original indices (prefix only)
__device__ int   g_nvalid[kB];
__device__ float g_qall[kL * kD];      // z @ Wq^T
__device__ float g_qk[kL * kD];        // qall @ Wk
__device__ float g_U[kB * kL * kD];    // s_l / denom (0 if empty segment)
__device__ float g_denom[kB * kL];
__device__ float g_Z[kB * kL * kD];    // Zattn

__device__ __forceinline__ float dot4(float4 a, float4 b) {
    return a.x * b.x + a.y * b.y + a.z * b.z + a.w * b.w;
}
__device__ __forceinline__ float sum4(float4 a) { return a.x + a.y + a.z + a.w; }

// ---------------- mask dtype detection -------------------------------------
// View the first 8192 uint32 words of the mask buffer. If mask is int32(0/1),
// all words are 0/1. If float32(0.0/1.0), all words are 0 or 0x3F800000.
// If uint8, packed bytes essentially never satisfy either (random data).
__global__ void detect_mask_kind_k(const unsigned int* __restrict__ m) {
    __shared__ int iok_s, fok_s;
    if (threadIdx.x == 0) { iok_s = 1; fok_s = 1; }
    __syncthreads();
    int iok = 1, fok = 1;
    for (int i = threadIdx.x; i < (kB * kN) / 4; i += blockDim.x) {
        unsigned v = m[i];
        if (!(v == 0u || v == 1u)) iok = 0;
        if (!(v == 0u || v == 0x3F800000u)) fok = 0;
    }
    if (!iok) atomicAnd(&iok_s, 0);
    if (!fok) atomicAnd(&fok_s, 0);
    __syncthreads();
    if (threadIdx.x == 0) g_mask_kind = iok_s ? 1 : (fok_s ? 2 : 0);
}

__device__ __forceinline__ bool mask_at(const void* m, int idx, int kind) {
    if (kind == 1) return ((const int*)m)[idx] != 0;
    if (kind == 2) return ((const float*)m)[idx] != 0.0f;
    return ((const unsigned char*)m)[idx] != 0;
}

// ---------------- stable compaction: valid indices first -------------------
__global__ __launch_bounds__(1024) void build_order_k(const void* __restrict__ mask) {
    const int b = blockIdx.x;
    const int t = threadIdx.x;
    const int kind = g_mask_kind;
    const int base = b * kN + t * 4;
    bool v[4];
    int c = 0;
#pragma unroll
    for (int j = 0; j < 4; j++) { v[j] = !mask_at(mask, base + j, kind); c += v[j] ? 1 : 0; }

    __shared__ int sc[1024];
    sc[t] = c;
    __syncthreads();
    // Hillis-Steele inclusive scan
    for (int off = 1; off < 1024; off <<= 1) {
        int x = (t >= off) ? sc[t - off] : 0;
        __syncthreads();
        sc[t] += x;
        __syncthreads();
    }
    int pos = sc[t] - c;  // exclusive prefix
#pragma unroll
    for (int j = 0; j < 4; j++) {
        if (v[j]) g_order[b * kN + pos++] = t * 4 + j;
    }
    if (t == 1023) g_nvalid[b] = sc[1023];
}

// ---------------- qall = z @ Wq^T : warp per output element ----------------
__global__ __launch_bounds__(256) void qall_k(const float* __restrict__ z,
                                              const float* __restrict__ Wq) {
    const int gw = (blockIdx.x * 256 + threadIdx.x) >> 5;  // 0 .. L*D-1
    const int lane = threadIdx.x & 31;
    const int l = gw >> 9;          // /512
    const int d = gw & (kD - 1);
    const float4* wr = (const float4*)(Wq + (size_t)d * kD);
    const float4* zr = (const float4*)(z + (size_t)l * kD);
    float a0 = dot4(wr[lane], zr[lane]);
    float a1 = dot4(wr[lane + 32], zr[lane + 32]);
    float a2 = dot4(wr[lane + 64], zr[lane + 64]);
    float a3 = dot4(wr[lane + 96], zr[lane + 96]);
    float acc = (a0 + a1) + (a2 + a3);
#pragma unroll
    for (int o = 16; o; o >>= 1) acc += __shfl_xor_sync(0xffffffffu, acc, o);
    if (lane == 0) g_qall[gw] = acc;
}

// ---------------- qk = qall @ Wk : block per l, axpy over rows of Wk --------
__global__ __launch_bounds__(512) void qk_k(const float* __restrict__ Wk) {
    const int l = blockIdx.x;
    const int e = threadIdx.x;
    __shared__ float a_s[kD];
    a_s[e] = g_qall[l * kD + e];
    __syncthreads();
    float a0 = 0.f, a1 = 0.f, a2 = 0.f, a3 = 0.f;
#pragma unroll 4
    for (int d = 0; d < kD; d += 4) {
        a0 = fmaf(a_s[d + 0], Wk[(size_t)(d + 0) * kD + e], a0);
        a1 = fmaf(a_s[d + 1], Wk[(size_t)(d + 1) * kD + e], a1);
        a2 = fmaf(a_s[d + 2], Wk[(size_t)(d + 2) * kD + e], a2);
        a3 = fmaf(a_s[d + 3], Wk[(size_t)(d + 3) * kD + e], a3);
    }
    g_qk[l * kD + e] = (a0 + a1) + (a2 + a3);
}

// ---------------- fused LN + logits + segment softmax accumulate -----------
// One block per (sample b, segment l). Warp per token; single pass with
// fixed softmax shift of 5 (logits clipped to [-5,5], ratios invariant).
__global__ __launch_bounds__(512) void attn_k(const float* __restrict__ feats) {
    const int l = blockIdx.x, b = blockIdx.y;
    const int tid = threadIdx.x, wid = tid >> 5, lane = tid & 31;

    __shared__ float qk_s[kD];
    __shared__ float s_part[16][kD];
    __shared__ float den_part[16];

    qk_s[tid] = g_qk[l * kD + tid];
    __syncthreads();

    // per-lane slice of qk (d = 4*(lane+32q)+c) and its total sum
    float4 qk4[4];
    float qks = 0.f;
#pragma unroll
    for (int q = 0; q < 4; q++) {
        qk4[q] = *(const float4*)&qk_s[(lane + 32 * q) * 4];
        qks += sum4(qk4[q]);
    }
#pragma unroll
    for (int o = 16; o; o >>= 1) qks += __shfl_xor_sync(0xffffffffu, qks, o);

    const int nv = g_nvalid[b];
    int segsz = nv / kL; if (segsz < 1) segsz = 1;
    const int n_used = min(nv, kL * segsz);
    const int t0 = l * segsz;
    const int t1 = min(t0 + segsz, n_used);

    float4 sac[4];
#pragma unroll
    for (int q = 0; q < 4; q++) sac[q] = make_float4(0.f, 0.f, 0.f, 0.f);
    float dac = 0.f;

    for (int t = t0 + wid; t < t1; t += 16) {
        const int orig = g_order[b * kN + t];
        const float4* row = (const float4*)(feats + ((size_t)b * kN + orig) * kD);
        float4 v[4];
        float sm = 0.f, sq = 0.f, dt = 0.f;
#pragma unroll
        for (int q = 0; q < 4; q++) {
            v[q] = row[lane + 32 * q];
            sm += sum4(v[q]);
            sq += dot4(v[q], v[q]);
            dt += dot4(v[q], qk4[q]);
        }
#pragma unroll
        for (int o = 16; o; o >>= 1) {
            sm += __shfl_xor_sync(0xffffffffu, sm, o);
            sq += __shfl_xor_sync(0xffffffffu, sq, o);
            dt += __shfl_xor_sync(0xffffffffu, dt, o);
        }
        const float mu = sm * (1.0f / kD);
        const float var = sq * (1.0f / kD) - mu * mu;
        const float rstd = rsqrtf(var + 1e-5f);
        float logit = (dt - mu * qks) * rstd * kInvTemp;
        logit = fminf(5.0f, fmaxf(-5.0f, logit));
        const float w = expf(logit - 5.0f);
        const float wr = w * rstd;
        const float wm = wr * mu;
#pragma unroll
        for (int q = 0; q < 4; q++) {
            sac[q].x += wr * v[q].x - wm;
            sac[q].y += wr * v[q].y - wm;
            sac[q].z += wr * v[q].z - wm;
            sac[q].w += wr * v[q].w - wm;
        }
        dac += w;
    }

#pragma unroll
    for (int q = 0; q < 4; q++)
        *(float4*)&s_part[wid][(lane + 32 * q) * 4] = sac[q];
    if (lane == 0) den_part[wid] = dac;
    __syncthreads();

    float s = 0.f;
#pragma unroll
    for (int w = 0; w < 16; w++) s += s_part[w][tid];
    float den = 0.f;
#pragma unroll
    for (int w = 0; w < 16; w++) den += den_part[w];

    const int m = b * kL + l;
    g_U[(size_t)m * kD + tid] = (den > 0.f) ? (s / den) : 0.f;
    if (tid == 0) g_denom[m] = den;
}

// ---------------- tiled SGEMM: C[M,512] = A[M,512] @ W^T (+ epilogue) ------
// BM=32, BN=64, BK=16, 256 threads, 2x4 micro-tile. EPI: 1 = replace empty
// segments with z rows (Wv apply); 2 = +bo and replace nvalid==0 samples (Wo).
template <int EPI>
__global__ __launch_bounds__(256) void gemm_nt_k(const float* __restrict__ A,
                                                 const float* __restrict__ W,
                                                 float* __restrict__ C,
                                                 const float* __restrict__ z,
                                                 const float* __restrict__ den,
                                                 const float* __restrict__ bo) {
    __shared__ float As[16][32];
    __shared__ float Bs[16][64];
    const int tid = threadIdx.x;
    const int m0 = blockIdx.y * 32, n0 = blockIdx.x * 64;
    const int tx = tid & 15, ty = tid >> 4;
    float acc[2][4] = {};

    for (int k0 = 0; k0 < kD; k0 += 16) {
        if (tid < 128) {
            const int lr = tid >> 2, lk = (tid & 3) * 4;
            float4 a = *(const float4*)&A[(size_t)(m0 + lr) * kD + k0 + lk];
            As[lk + 0][lr] = a.x; As[lk + 1][lr] = a.y;
            As[lk + 2][lr] = a.z; As[lk + 3][lr] = a.w;
        }
        {
            const int lr = tid >> 2, lk = (tid & 3) * 4;
            float4 bb = *(const float4*)&W[(size_t)(n0 + lr) * kD + k0 + lk];
            Bs[lk + 0][lr] = bb.x; Bs[lk + 1][lr] = bb.y;
            Bs[lk + 2][lr] = bb.z; Bs[lk + 3][lr] = bb.w;
        }
        __syncthreads();
#pragma unroll
        for (int k = 0; k < 16; k++) {
            float2 av = *(const float2*)&As[k][ty * 2];
            float4 bv = *(const float4*)&Bs[k][tx * 4];
            acc[0][0] += av.x * bv.x; acc[0][1] += av.x * bv.y;
            acc[0][2] += av.x * bv.z; acc[0][3] += av.x * bv.w;
            acc[1][0] += av.y * bv.x; acc[1][1] += av.y * bv.y;
            acc[1][2] += av.y * bv.z; acc[1][3] += av.y * bv.w;
        }
        __syncthreads();
    }

#pragma unroll
    for (int i = 0; i < 2; i++) {
        const int m = m0 + ty * 2 + i;
        bool repl = false;
        if (EPI == 1) repl = (den[m] <= 0.f);
        if (EPI == 2) repl = (g_nvalid[m / kL] == 0);
        const float* zr = z + (size_t)(m % kL) * kD;
#pragma unroll
        for (int j = 0; j < 4; j++) {
            const int n = n0 + tx * 4 + j;
            float v = acc[i][j];
            if (EPI == 2) v += bo[n];
            if (repl) v = zr[n];
            C[(size_t)m * kD + n] = v;
        }
    }
}

// ---------------------------------------------------------------------------
extern "C" void kernel_launch(void* const* d_in, const int* in_sizes, int n_in,
                              void* d_out, int out_size) {
    (void)in_sizes; (void)n_in; (void)out_size;
    const float* feats = (const float*)d_in[0];
    // d_in[1] = coords (unused by the reference output)
    const void*  mask  = d_in[2];
    const float* z     = (const float*)d_in[3];
    const float* Wq    = (const float*)d_in[4];
    const float* Wk    = (const float*)d_in[5];
    const float* Wv    = (const float*)d_in[6];
    const float* Wo    = (const float*)d_in[7];
    const float* bo    = (const float*)d_in[8];
    float* out = (float*)d_out;

    float *pU = nullptr, *pZ = nullptr, *pden = nullptr;
    cudaGetSymbolAddress((void**)&pU, g_U);
    cudaGetSymbolAddress((void**)&pZ, g_Z);
    cudaGetSymbolAddress((void**)&pden, g_denom);

    detect_mask_kind_k<<<1, 256>>>((const unsigned int*)mask);
    build_order_k<<<kB, 1024>>>(mask);
    qall_k<<<(kL * kD) / 8, 256>>>(z, Wq);
    qk_k<<<kL, 512>>>(Wk);
    attn_k<<<dim3(kL, kB), 512>>>(feats);
    gemm_nt_k<1><<<dim3(kD / 64, (kB * kL) / 32), 256>>>(pU, Wv, pZ, z, pden, nullptr);
    gemm_nt_k<2><<<dim3(kD / 64, (kB * kL) / 32), 256>>>(pZ, Wo, out, z, nullptr, bo);
}

// round 2
// speedup vs baseline: 1.0658x; 1.0658x over previous
#include <cuda_runtime.h>
#include <math.h>

namespace {
constexpr int kB = 8;
constexpr int kN = 4096;
constexpr int kD = 512;
constexpr int kL = 64;
constexpr float kInvTemp = 0.044194173824159216f; // 1/sqrt(512)
}

// ---------------- scratch (device globals; no allocation allowed) ----------
__device__ int   g_mask_kind;          // 0=uint8, 1=int32, 2=float32
__device__ int   g_order[kB * kN];     // sorted-valid original indices (prefix only)
__device__ int   g_nvalid[kB];
__device__ float g_qall[kL * kD];      // z @ Wq^T
__device__ float g_qk[kL * kD];        // qall @ Wk (atomically accumulated)
__device__ float g_U[kB * kL * kD];    // s_l / denom (0 if empty segment)
__device__ float g_denom[kB * kL];
__device__ float g_Z[kB * kL * kD];    // Zattn

__device__ __forceinline__ float dot4(float4 a, float4 b) {
    return a.x * b.x + a.y * b.y + a.z * b.z + a.w * b.w;
}
__device__ __forceinline__ float sum4(float4 a) { return a.x + a.y + a.z + a.w; }

// ---------------- mask dtype detection + qk zero-init -----------------------
// View the first 8192 uint32 words of the mask buffer. If mask is int32(0/1),
// all words are 0/1. If float32(0.0/1.0), all words are 0 or 0x3F800000.
// If uint8, packed bytes essentially never satisfy either (random data).
// Also zeroes g_qk for the split-K accumulation downstream (same stream ->
// ordering guaranteed).
__global__ void detect_mask_kind_k(const unsigned int* __restrict__ m) {
    __shared__ int iok_s, fok_s;
    if (threadIdx.x == 0) { iok_s = 1; fok_s = 1; }
    __syncthreads();
    int iok = 1, fok = 1;
    for (int i = threadIdx.x; i < (kB * kN) / 4; i += blockDim.x) {
        unsigned v = m[i];
        if (!(v == 0u || v == 1u)) iok = 0;
        if (!(v == 0u || v == 0x3F800000u)) fok = 0;
    }
    if (!iok) atomicAnd(&iok_s, 0);
    if (!fok) atomicAnd(&fok_s, 0);
    // zero the qk accumulator (32K floats across 256 threads)
    float4 z4 = make_float4(0.f, 0.f, 0.f, 0.f);
    for (int i = threadIdx.x; i < (kL * kD) / 4; i += blockDim.x)
        ((float4*)g_qk)[i] = z4;
    __syncthreads();
    if (threadIdx.x == 0) g_mask_kind = iok_s ? 1 : (fok_s ? 2 : 0);
}

__device__ __forceinline__ bool mask_at(const void* m, int idx, int kind) {
    if (kind == 1) return ((const int*)m)[idx] != 0;
    if (kind == 2) return ((const float*)m)[idx] != 0.0f;
    return ((const unsigned char*)m)[idx] != 0;
}

// ---------------- stable compaction: valid indices first -------------------
__global__ __launch_bounds__(1024) void build_order_k(const void* __restrict__ mask) {
    const int b = blockIdx.x;
    const int t = threadIdx.x;
    const int kind = g_mask_kind;
    const int base = b * kN + t * 4;
    bool v[4];
    int c = 0;
#pragma unroll
    for (int j = 0; j < 4; j++) { v[j] = !mask_at(mask, base + j, kind); c += v[j] ? 1 : 0; }

    __shared__ int sc[1024];
    sc[t] = c;
    __syncthreads();
    // Hillis-Steele inclusive scan
    for (int off = 1; off < 1024; off <<= 1) {
        int x = (t >= off) ? sc[t - off] : 0;
        __syncthreads();
        sc[t] += x;
        __syncthreads();
    }
    int pos = sc[t] - c;  // exclusive prefix
#pragma unroll
    for (int j = 0; j < 4; j++) {
        if (v[j]) g_order[b * kN + pos++] = t * 4 + j;
    }
    if (t == 1023) g_nvalid[b] = sc[1023];
}

// ---------------- qall = z @ Wq^T : warp per output element ----------------
__global__ __launch_bounds__(256) void qall_k(const float* __restrict__ z,
                                              const float* __restrict__ Wq) {
    const int gw = (blockIdx.x * 256 + threadIdx.x) >> 5;  // 0 .. L*D-1
    const int lane = threadIdx.x & 31;
    const int l = gw >> 9;          // /512
    const int d = gw & (kD - 1);
    const float4* wr = (const float4*)(Wq + (size_t)d * kD);
    const float4* zr = (const float4*)(z + (size_t)l * kD);
    float a0 = dot4(wr[lane], zr[lane]);
    float a1 = dot4(wr[lane + 32], zr[lane + 32]);
    float a2 = dot4(wr[lane + 64], zr[lane + 64]);
    float a3 = dot4(wr[lane + 96], zr[lane + 96]);
    float acc = (a0 + a1) + (a2 + a3);
#pragma unroll
    for (int o = 16; o; o >>= 1) acc += __shfl_xor_sync(0xffffffffu, acc, o);
    if (lane == 0) g_qall[gw] = acc;
}

// ---------------- qk = qall @ Wk : SPLIT-K over the 512 reduction ----------
// grid (l=64, kslice=8): each block reduces a 64-row slice of Wk and
// atomically accumulates into g_qk. 512 blocks -> full chip, latency hidden.
__global__ __launch_bounds__(512) void qk_k(const float* __restrict__ Wk) {
    const int l = blockIdx.x;
    const int ks = blockIdx.y;
    const int e = threadIdx.x;
    __shared__ float a_s[64];
    if (e < 64) a_s[e] = g_qall[l * kD + ks * 64 + e];
    __syncthreads();
    const float* W = Wk + (size_t)(ks * 64) * kD + e;
    float a0 = 0.f, a1 = 0.f, a2 = 0.f, a3 = 0.f;
#pragma unroll
    for (int d = 0; d < 64; d += 4) {
        a0 = fmaf(a_s[d + 0], W[(size_t)(d + 0) * kD], a0);
        a1 = fmaf(a_s[d + 1], W[(size_t)(d + 1) * kD], a1);
        a2 = fmaf(a_s[d + 2], W[(size_t)(d + 2) * kD], a2);
        a3 = fmaf(a_s[d + 3], W[(size_t)(d + 3) * kD], a3);
    }
    atomicAdd(&g_qk[l * kD + e], (a0 + a1) + (a2 + a3));
}

// ---------------- fused LN + logits + segment softmax accumulate -----------
// One block per (sample b, segment l). Warp per token; single pass with
// fixed softmax shift of 5 (logits clipped to [-5,5], ratios invariant).
__global__ __launch_bounds__(512) void attn_k(const float* __restrict__ feats) {
    const int l = blockIdx.x, b = blockIdx.y;
    const int tid = threadIdx.x, wid = tid >> 5, lane = tid & 31;

    __shared__ float qk_s[kD];
    __shared__ float s_part[16][kD];
    __shared__ float den_part[16];

    qk_s[tid] = g_qk[l * kD + tid];
    __syncthreads();

    // per-lane slice of qk (d = 4*(lane+32q)+c) and its total sum
    float4 qk4[4];
    float qks = 0.f;
#pragma unroll
    for (int q = 0; q < 4; q++) {
        qk4[q] = *(const float4*)&qk_s[(lane + 32 * q) * 4];
        qks += sum4(qk4[q]);
    }
#pragma unroll
    for (int o = 16; o; o >>= 1) qks += __shfl_xor_sync(0xffffffffu, qks, o);

    const int nv = g_nvalid[b];
    int segsz = nv / kL; if (segsz < 1) segsz = 1;
    const int n_used = min(nv, kL * segsz);
    const int t0 = l * segsz;
    const int t1 = min(t0 + segsz, n_used);

    float4 sac[4];
#pragma unroll
    for (int q = 0; q < 4; q++) sac[q] = make_float4(0.f, 0.f, 0.f, 0.f);
    float dac = 0.f;

    for (int t = t0 + wid; t < t1; t += 16) {
        const int orig = g_order[b * kN + t];
        const float4* row = (const float4*)(feats + ((size_t)b * kN + orig) * kD);
        float4 v[4];
        float sm = 0.f, sq = 0.f, dt = 0.f;
#pragma unroll
        for (int q = 0; q < 4; q++) {
            v[q] = row[lane + 32 * q];
            sm += sum4(v[q]);
            sq += dot4(v[q], v[q]);
            dt += dot4(v[q], qk4[q]);
        }
#pragma unroll
        for (int o = 16; o; o >>= 1) {
            sm += __shfl_xor_sync(0xffffffffu, sm, o);
            sq += __shfl_xor_sync(0xffffffffu, sq, o);
            dt += __shfl_xor_sync(0xffffffffu, dt, o);
        }
        const float mu = sm * (1.0f / kD);
        const float var = sq * (1.0f / kD) - mu * mu;
        const float rstd = rsqrtf(var + 1e-5f);
        float logit = (dt - mu * qks) * rstd * kInvTemp;
        logit = fminf(5.0f, fmaxf(-5.0f, logit));
        const float w = expf(logit - 5.0f);
        const float wr = w * rstd;
        const float wm = wr * mu;
#pragma unroll
        for (int q = 0; q < 4; q++) {
            sac[q].x += wr * v[q].x - wm;
            sac[q].y += wr * v[q].y - wm;
            sac[q].z += wr * v[q].z - wm;
            sac[q].w += wr * v[q].w - wm;
        }
        dac += w;
    }

#pragma unroll
    for (int q = 0; q < 4; q++)
        *(float4*)&s_part[wid][(lane + 32 * q) * 4] = sac[q];
    if (lane == 0) den_part[wid] = dac;
    __syncthreads();

    float s = 0.f;
#pragma unroll
    for (int w = 0; w < 16; w++) s += s_part[w][tid];
    float den = 0.f;
#pragma unroll
    for (int w = 0; w < 16; w++) den += den_part[w];

    const int m = b * kL + l;
    g_U[(size_t)m * kD + tid] = (den > 0.f) ? (s / den) : 0.f;
    if (tid == 0) g_denom[m] = den;
}

// ---------------- tiled SGEMM: C[M,512] = A[M,512] @ W^T (+ epilogue) ------
// BM=32, BN=64, BK=16, 256 threads, 2x4 micro-tile. EPI: 1 = replace empty
// segments with z rows (Wv apply); 2 = +bo and replace nvalid==0 samples (Wo).
template <int EPI>
__global__ __launch_bounds__(256) void gemm_nt_k(const float* __restrict__ A,
                                                 const float* __restrict__ W,
                                                 float* __restrict__ C,
                                                 const float* __restrict__ z,
                                                 const float* __restrict__ den,
                                                 const float* __restrict__ bo) {
    __shared__ float As[16][32];
    __shared__ float Bs[16][64];
    const int tid = threadIdx.x;
    const int m0 = blockIdx.y * 32, n0 = blockIdx.x * 64;
    const int tx = tid & 15, ty = tid >> 4;
    float acc[2][4] = {};

    for (int k0 = 0; k0 < kD; k0 += 16) {
        if (tid < 128) {
            const int lr = tid >> 2, lk = (tid & 3) * 4;
            float4 a = *(const float4*)&A[(size_t)(m0 + lr) * kD + k0 + lk];
            As[lk + 0][lr] = a.x; As[lk + 1][lr] = a.y;
            As[lk + 2][lr] = a.z; As[lk + 3][lr] = a.w;
        }
        {
            const int lr = tid >> 2, lk = (tid & 3) * 4;
            float4 bb = *(const float4*)&W[(size_t)(n0 + lr) * kD + k0 + lk];
            Bs[lk + 0][lr] = bb.x; Bs[lk + 1][lr] = bb.y;
            Bs[lk + 2][lr] = bb.z; Bs[lk + 3][lr] = bb.w;
        }
        __syncthreads();
#pragma unroll
        for (int k = 0; k < 16; k++) {
            float2 av = *(const float2*)&As[k][ty * 2];
            float4 bv = *(const float4*)&Bs[k][tx * 4];
            acc[0][0] += av.x * bv.x; acc[0][1] += av.x * bv.y;
            acc[0][2] += av.x * bv.z; acc[0][3] += av.x * bv.w;
            acc[1][0] += av.y * bv.x; acc[1][1] += av.y * bv.y;
            acc[1][2] += av.y * bv.z; acc[1][3] += av.y * bv.w;
        }
        __syncthreads();
    }

#pragma unroll
    for (int i = 0; i < 2; i++) {
        const int m = m0 + ty * 2 + i;
        bool repl = false;
        if (EPI == 1) repl = (den[m] <= 0.f);
        if (EPI == 2) repl = (g_nvalid[m / kL] == 0);
        const float* zr = z + (size_t)(m % kL) * kD;
#pragma unroll
        for (int j = 0; j < 4; j++) {
            const int n = n0 + tx * 4 + j;
            float v = acc[i][j];
            if (EPI == 2) v += bo[n];
            if (repl) v = zr[n];
            C[(size_t)m * kD + n] = v;
        }
    }
}

// ---------------------------------------------------------------------------
extern "C" void kernel_launch(void* const* d_in, const int* in_sizes, int n_in,
                              void* d_out, int out_size) {
    (void)in_sizes; (void)n_in; (void)out_size;
    const float* feats = (const float*)d_in[0];
    // d_in[1] = coords (unused by the reference output)
    const void*  mask  = d_in[2];
    const float* z     = (const float*)d_in[3];
    const float* Wq    = (const float*)d_in[4];
    const float* Wk    = (const float*)d_in[5];
    const float* Wv    = (const float*)d_in[6];
    const float* Wo    = (const float*)d_in[7];
    const float* bo    = (const float*)d_in[8];
    float* out = (float*)d_out;

    float *pU = nullptr, *pZ = nullptr, *pden = nullptr;
    cudaGetSymbolAddress((void**)&pU, g_U);
    cudaGetSymbolAddress((void**)&pZ, g_Z);
    cudaGetSymbolAddress((void**)&pden, g_denom);

    detect_mask_kind_k<<<1, 256>>>((const unsigned int*)mask);
    build_order_k<<<kB, 1024>>>(mask);
    qall_k<<<(kL * kD) / 8, 256>>>(z, Wq);
    qk_k<<<dim3(kL, 8), 512>>>(Wk);
    attn_k<<<dim3(kL, kB), 512>>>(feats);
    gemm_nt_k<1><<<dim3(kD / 64, (kB * kL) / 32), 256>>>(pU, Wv, pZ, z, pden, nullptr);
    gemm_nt_k<2><<<dim3(kD / 64, (kB * kL) / 32), 256>>>(pZ, Wo, out, z, nullptr, bo);
}

// round 3
// speedup vs baseline: 1.1655x; 1.0935x over previous
#include <cuda_runtime.h>
#include <math.h>

namespace {
constexpr int kB = 8;
constexpr int kN = 4096;
constexpr int kD = 512;
constexpr int kL = 64;
constexpr int kKS = 8;  // qk split-k slices
constexpr float kInvTemp = 0.044194173824159216f; // 1/sqrt(512)
}

// ---------------- scratch (device globals; no allocation allowed) ----------
__device__ int   g_order[kB * kN];       // sorted-valid original indices (prefix only)
__device__ int   g_nvalid[kB];
__device__ float g_qall[kL * kD];        // z @ Wq^T
__device__ float g_qkp[kKS * kL * kD];   // qk split-k partials
__device__ float g_U[kB * kL * kD];      // s_l / denom (0 if empty segment)
__device__ float g_denom[kB * kL];
__device__ float g_Z[kB * kL * kD];      // Zattn

__device__ __forceinline__ float dot4(float4 a, float4 b) {
    return a.x * b.x + a.y * b.y + a.z * b.z + a.w * b.w;
}
__device__ __forceinline__ float sum4(float4 a) { return a.x + a.y + a.z + a.w; }

__device__ __forceinline__ bool mask_at(const void* m, int idx, int kind) {
    if (kind == 1) return ((const int*)m)[idx] != 0;
    if (kind == 2) return ((const float*)m)[idx] != 0.0f;
    return ((const unsigned char*)m)[idx] != 0;
}

// ======================= K1: fused build_order + qall =======================
// Blocks 0..7: per-sample mask-dtype detect + stable compaction.
// Blocks 8..4103: warp-per-output qall = z @ Wq^T.
__global__ __launch_bounds__(256) void k1_order_qall(const void* __restrict__ mask,
                                                     const float* __restrict__ z,
                                                     const float* __restrict__ Wq) {
    const int tid = threadIdx.x;
    const int wid = tid >> 5, lane = tid & 31;

    if (blockIdx.x < kB) {
        // ---- build_order for sample b ----
        const int b = blockIdx.x;

        // dtype detect from this sample's first 1024 words (in-range for any dtype).
        // int32(0/1) -> words 0/1; float32(0/1.0) -> 0/0x3F800000; uint8 packed
        // bools essentially never satisfy either unless all-zero (then any
        // interpretation gives "all valid" -> identical result).
        const unsigned* mw = (const unsigned*)mask;
        int iok = 1, fok = 1;
        for (int i = tid; i < 1024; i += 256) {
            unsigned v = mw[b * 1024 + i];
            iok &= (v <= 1u);
            fok &= (v == 0u || v == 0x3F800000u);
        }
        iok = __syncthreads_and(iok);
        fok = __syncthreads_and(fok);
        const int kind = iok ? 1 : (fok ? 2 : 0);

        // 16 entries per thread, contiguous -> stable order via prefix scan
        const int base = tid * 16;
        bool v[16];
        int c = 0;
#pragma unroll
        for (int j = 0; j < 16; j++) {
            v[j] = !mask_at(mask, b * kN + base + j, kind);
            c += v[j] ? 1 : 0;
        }
        // warp inclusive scan
        int inc = c;
#pragma unroll
        for (int o = 1; o < 32; o <<= 1) {
            int x = __shfl_up_sync(0xffffffffu, inc, o);
            if (lane >= o) inc += x;
        }
        __shared__ int wsum[8];
        if (lane == 31) wsum[wid] = inc;
        __syncthreads();
        __shared__ int woff[8];
        if (tid < 8) {
            int s = 0;
            for (int w = 0; w < 8; w++) { woff[w] = s; s += wsum[w]; }
            if (tid == 0) g_nvalid[b] = s;
        }
        __syncthreads();
        int pos = woff[wid] + inc - c;  // exclusive prefix
#pragma unroll
        for (int j = 0; j < 16; j++) {
            if (v[j]) g_order[b * kN + pos++] = base + j;
        }
    } else {
        // ---- qall: warp per output element ----
        const int gw = (blockIdx.x - kB) * 8 + wid;  // 0 .. L*D-1
        const int l = gw >> 9;
        const int d = gw & (kD - 1);
        const float4* wr = (const float4*)(Wq + (size_t)d * kD);
        const float4* zr = (const float4*)(z + (size_t)l * kD);
        float a0 = dot4(wr[lane], zr[lane]);
        float a1 = dot4(wr[lane + 32], zr[lane + 32]);
        float a2 = dot4(wr[lane + 64], zr[lane + 64]);
        float a3 = dot4(wr[lane + 96], zr[lane + 96]);
        float acc = (a0 + a1) + (a2 + a3);
#pragma unroll
        for (int o = 16; o; o >>= 1) acc += __shfl_xor_sync(0xffffffffu, acc, o);
        if (lane == 0) g_qall[gw] = acc;
    }
}

// ======================= K2: qk split-k partials ============================
// grid (l=64, ks=8): block reduces a 64-row slice of Wk, plain partial store.
__global__ __launch_bounds__(512) void qk_k(const float* __restrict__ Wk) {
    const int l = blockIdx.x;
    const int ks = blockIdx.y;
    const int e = threadIdx.x;
    __shared__ float a_s[64];
    if (e < 64) a_s[e] = g_qall[l * kD + ks * 64 + e];
    __syncthreads();
    const float* W = Wk + (size_t)(ks * 64) * kD + e;
    float a0 = 0.f, a1 = 0.f, a2 = 0.f, a3 = 0.f;
#pragma unroll
    for (int d = 0; d < 64; d += 4) {
        a0 = fmaf(a_s[d + 0], W[(size_t)(d + 0) * kD], a0);
        a1 = fmaf(a_s[d + 1], W[(size_t)(d + 1) * kD], a1);
        a2 = fmaf(a_s[d + 2], W[(size_t)(d + 2) * kD], a2);
        a3 = fmaf(a_s[d + 3], W[(size_t)(d + 3) * kD], a3);
    }
    g_qkp[(ks * kL + l) * kD + e] = (a0 + a1) + (a2 + a3);
}

// ============ K3: fused LN + logits + segment softmax accumulate ============
// One block (256 thr, 8 warps) per (sample b, segment l). Warp per token,
// single pass with fixed softmax shift of 5 (logits clipped to [-5,5]).
__global__ __launch_bounds__(256) void attn_k(const float* __restrict__ feats) {
    const int l = blockIdx.x, b = blockIdx.y;
    const int tid = threadIdx.x, wid = tid >> 5, lane = tid & 31;

    __shared__ float qk_s[kD];
    __shared__ float s_part[8][kD];
    __shared__ float den_part[8];

    // stage qk[l] = sum of split-k partials
    for (int e = tid; e < kD; e += 256) {
        float s = 0.f;
#pragma unroll
        for (int ks = 0; ks < kKS; ks++) s += g_qkp[(ks * kL + l) * kD + e];
        qk_s[e] = s;
    }
    __syncthreads();

    // per-lane slice of qk (d = 4*(lane+32q)+c) and its total sum
    float4 qk4[4];
    float qks = 0.f;
#pragma unroll
    for (int q = 0; q < 4; q++) {
        qk4[q] = *(const float4*)&qk_s[(lane + 32 * q) * 4];
        qks += sum4(qk4[q]);
    }
#pragma unroll
    for (int o = 16; o; o >>= 1) qks += __shfl_xor_sync(0xffffffffu, qks, o);

    const int nv = g_nvalid[b];
    int segsz = nv / kL; if (segsz < 1) segsz = 1;
    const int n_used = min(nv, kL * segsz);
    const int t0 = l * segsz;
    const int t1 = min(t0 + segsz, n_used);

    float4 sac[4];
#pragma unroll
    for (int q = 0; q < 4; q++) sac[q] = make_float4(0.f, 0.f, 0.f, 0.f);
    float dac = 0.f;

    for (int t = t0 + wid; t < t1; t += 8) {
        const int orig = g_order[b * kN + t];
        const float4* row = (const float4*)(feats + ((size_t)b * kN + orig) * kD);
        float4 v[4];
        float sm = 0.f, sq = 0.f, dt = 0.f;
#pragma unroll
        for (int q = 0; q < 4; q++) {
            v[q] = row[lane + 32 * q];
            sm += sum4(v[q]);
            sq += dot4(v[q], v[q]);
            dt += dot4(v[q], qk4[q]);
        }
#pragma unroll
        for (int o = 16; o; o >>= 1) {
            sm += __shfl_xor_sync(0xffffffffu, sm, o);
            sq += __shfl_xor_sync(0xffffffffu, sq, o);
            dt += __shfl_xor_sync(0xffffffffu, dt, o);
        }
        const float mu = sm * (1.0f / kD);
        const float var = sq * (1.0f / kD) - mu * mu;
        const float rstd = rsqrtf(var + 1e-5f);
        float logit = (dt - mu * qks) * rstd * kInvTemp;
        logit = fminf(5.0f, fmaxf(-5.0f, logit));
        const float w = expf(logit - 5.0f);
        const float wr = w * rstd;
        const float wm = wr * mu;
#pragma unroll
        for (int q = 0; q < 4; q++) {
            sac[q].x += wr * v[q].x - wm;
            sac[q].y += wr * v[q].y - wm;
            sac[q].z += wr * v[q].z - wm;
            sac[q].w += wr * v[q].w - wm;
        }
        dac += w;
    }

#pragma unroll
    for (int q = 0; q < 4; q++)
        *(float4*)&s_part[wid][(lane + 32 * q) * 4] = sac[q];
    if (lane == 0) den_part[wid] = dac;
    __syncthreads();

    float den = 0.f;
#pragma unroll
    for (int w = 0; w < 8; w++) den += den_part[w];

    const int m = b * kL + l;
    for (int e = tid; e < kD; e += 256) {
        float s = 0.f;
#pragma unroll
        for (int w = 0; w < 8; w++) s += s_part[w][e];
        g_U[(size_t)m * kD + e] = (den > 0.f) ? (s / den) : 0.f;
    }
    if (tid == 0) g_denom[m] = den;
}

// ---------------- tiled SGEMM: C[M,512] = A[M,512] @ W^T (+ epilogue) ------
// BM=32, BN=64, BK=16, 256 threads, 2x4 micro-tile. EPI: 1 = replace empty
// segments with z rows (Wv apply); 2 = +bo and replace nvalid==0 samples (Wo).
template <int EPI>
__global__ __launch_bounds__(256) void gemm_nt_k(const float* __restrict__ A,
                                                 const float* __restrict__ W,
                                                 float* __restrict__ C,
                                                 const float* __restrict__ z,
                                                 const float* __restrict__ den,
                                                 const float* __restrict__ bo) {
    __shared__ float As[16][32];
    __shared__ float Bs[16][64];
    const int tid = threadIdx.x;
    const int m0 = blockIdx.y * 32, n0 = blockIdx.x * 64;
    const int tx = tid & 15, ty = tid >> 4;
    float acc[2][4] = {};

    for (int k0 = 0; k0 < kD; k0 += 16) {
        if (tid < 128) {
            const int lr = tid >> 2, lk = (tid & 3) * 4;
            float4 a = *(const float4*)&A[(size_t)(m0 + lr) * kD + k0 + lk];
            As[lk + 0][lr] = a.x; As[lk + 1][lr] = a.y;
            As[lk + 2][lr] = a.z; As[lk + 3][lr] = a.w;
        }
        {
            const int lr = tid >> 2, lk = (tid & 3) * 4;
            float4 bb = *(const float4*)&W[(size_t)(n0 + lr) * kD + k0 + lk];
            Bs[lk + 0][lr] = bb.x; Bs[lk + 1][lr] = bb.y;
            Bs[lk + 2][lr] = bb.z; Bs[lk + 3][lr] = bb.w;
        }
        __syncthreads();
#pragma unroll
        for (int k = 0; k < 16; k++) {
            float2 av = *(const float2*)&As[k][ty * 2];
            float4 bv = *(const float4*)&Bs[k][tx * 4];
            acc[0][0] += av.x * bv.x; acc[0][1] += av.x * bv.y;
            acc[0][2] += av.x * bv.z; acc[0][3] += av.x * bv.w;
            acc[1][0] += av.y * bv.x; acc[1][1] += av.y * bv.y;
            acc[1][2] += av.y * bv.z; acc[1][3] += av.y * bv.w;
        }
        __syncthreads();
    }

#pragma unroll
    for (int i = 0; i < 2; i++) {
        const int m = m0 + ty * 2 + i;
        bool repl = false;
        if (EPI == 1) repl = (den[m] <= 0.f);
        if (EPI == 2) repl = (g_nvalid[m / kL] == 0);
        const float* zr = z + (size_t)(m % kL) * kD;
#pragma unroll
        for (int j = 0; j < 4; j++) {
            const int n = n0 + tx * 4 + j;
            float v = acc[i][j];
            if (EPI == 2) v += bo[n];
            if (repl) v = zr[n];
            C[(size_t)m * kD + n] = v;
        }
    }
}

// ---------------------------------------------------------------------------
extern "C" void kernel_launch(void* const* d_in, const int* in_sizes, int n_in,
                              void* d_out, int out_size) {
    (void)in_sizes; (void)n_in; (void)out_size;
    const float* feats = (const float*)d_in[0];
    // d_in[1] = coords (unused by the reference output)
    const void*  mask  = d_in[2];
    const float* z     = (const float*)d_in[3];
    const float* Wq    = (const float*)d_in[4];
    const float* Wk    = (const float*)d_in[5];
    const float* Wv    = (const float*)d_in[6];
    const float* Wo    = (const float*)d_in[7];
    const float* bo    = (const float*)d_in[8];
    float* out = (float*)d_out;

    float *pU = nullptr, *pZ = nullptr, *pden = nullptr;
    cudaGetSymbolAddress((void**)&pU, g_U);
    cudaGetSymbolAddress((void**)&pZ, g_Z);
    cudaGetSymbolAddress((void**)&pden, g_denom);

    k1_order_qall<<<kB + (kL * kD) / 8, 256>>>(mask, z, Wq);
    qk_k<<<dim3(kL, kKS), 512>>>(Wk);
    attn_k<<<dim3(kL, kB), 256>>>(feats);
    gemm_nt_k<1><<<dim3(kD / 64, (kB * kL) / 32), 256>>>(pU, Wv, pZ, z, pden, nullptr);
    gemm_nt_k<2><<<dim3(kD / 64, (kB * kL) / 32), 256>>>(pZ, Wo, out, z, nullptr, bo);
}

// round 4
// speedup vs baseline: 1.3298x; 1.1410x over previous
#include <cuda_runtime.h>
#include <math.h>

namespace {
constexpr int kB = 8;
constexpr int kN = 4096;
constexpr int kD = 512;
constexpr int kL = 64;
constexpr int kKS = 8;   // qk split-k slices
constexpr int kM = kB * kL;           // 512 rows through the GEMMs
constexpr int kSlab = kM * kD;        // 262144 floats per partial slab
constexpr float kInvTemp = 0.044194173824159216f; // 1/sqrt(512)
}

// ---------------- scratch (device globals; no allocation allowed) ----------
__device__ int   g_order[kB * kN];       // sorted-valid original indices (prefix only)
__device__ int   g_nvalid[kB];
__device__ float g_qall[kL * kD];        // z @ Wq^T
__device__ float g_qkp[kKS * kL * kD];   // qk split-k partials
__device__ float g_U[kM * kD];           // s_l / denom (0 if empty segment)
__device__ float g_denom[kM];
__device__ float g_P1[2 * kSlab];        // gemm1 split-k partials (U @ Wv^T)
__device__ float g_P2[2 * kSlab];        // gemm2 split-k partials (Zattn @ Wo^T)

__device__ __forceinline__ float dot4(float4 a, float4 b) {
    return a.x * b.x + a.y * b.y + a.z * b.z + a.w * b.w;
}
__device__ __forceinline__ float sum4(float4 a) { return a.x + a.y + a.z + a.w; }

__device__ __forceinline__ bool mask_at(const void* m, int idx, int kind) {
    if (kind == 1) return ((const int*)m)[idx] != 0;
    if (kind == 2) return ((const float*)m)[idx] != 0.0f;
    return ((const unsigned char*)m)[idx] != 0;
}

// ======================= K1: fused build_order + qall =======================
__global__ __launch_bounds__(256) void k1_order_qall(const void* __restrict__ mask,
                                                     const float* __restrict__ z,
                                                     const float* __restrict__ Wq) {
    const int tid = threadIdx.x;
    const int wid = tid >> 5, lane = tid & 31;

    if (blockIdx.x < kB) {
        const int b = blockIdx.x;
        // dtype detect from this sample's first 1024 words (in-range for any dtype).
        const unsigned* mw = (const unsigned*)mask;
        int iok = 1, fok = 1;
        for (int i = tid; i < 1024; i += 256) {
            unsigned v = mw[b * 1024 + i];
            iok &= (v <= 1u);
            fok &= (v == 0u || v == 0x3F800000u);
        }
        iok = __syncthreads_and(iok);
        fok = __syncthreads_and(fok);
        const int kind = iok ? 1 : (fok ? 2 : 0);

        const int base = tid * 16;
        bool v[16];
        int c = 0;
#pragma unroll
        for (int j = 0; j < 16; j++) {
            v[j] = !mask_at(mask, b * kN + base + j, kind);
            c += v[j] ? 1 : 0;
        }
        int inc = c;
#pragma unroll
        for (int o = 1; o < 32; o <<= 1) {
            int x = __shfl_up_sync(0xffffffffu, inc, o);
            if (lane >= o) inc += x;
        }
        __shared__ int wsum[8];
        if (lane == 31) wsum[wid] = inc;
        __syncthreads();
        __shared__ int woff[8];
        if (tid < 8) {
            int s = 0;
            for (int w = 0; w < 8; w++) { woff[w] = s; s += wsum[w]; }
            if (tid == 0) g_nvalid[b] = s;
        }
        __syncthreads();
        int pos = woff[wid] + inc - c;
#pragma unroll
        for (int j = 0; j < 16; j++) {
            if (v[j]) g_order[b * kN + pos++] = base + j;
        }
    } else {
        const int gw = (blockIdx.x - kB) * 8 + wid;  // 0 .. L*D-1
        const int l = gw >> 9;
        const int d = gw & (kD - 1);
        const float4* wr = (const float4*)(Wq + (size_t)d * kD);
        const float4* zr = (const float4*)(z + (size_t)l * kD);
        float a0 = dot4(wr[lane], zr[lane]);
        float a1 = dot4(wr[lane + 32], zr[lane + 32]);
        float a2 = dot4(wr[lane + 64], zr[lane + 64]);
        float a3 = dot4(wr[lane + 96], zr[lane + 96]);
        float acc = (a0 + a1) + (a2 + a3);
#pragma unroll
        for (int o = 16; o; o >>= 1) acc += __shfl_xor_sync(0xffffffffu, acc, o);
        if (lane == 0) g_qall[gw] = acc;
    }
}

// ======================= K2: qk split-k partials ============================
__global__ __launch_bounds__(512) void qk_k(const float* __restrict__ Wk) {
    const int l = blockIdx.x;
    const int ks = blockIdx.y;
    const int e = threadIdx.x;
    __shared__ float a_s[64];
    if (e < 64) a_s[e] = g_qall[l * kD + ks * 64 + e];
    __syncthreads();
    const float* W = Wk + (size_t)(ks * 64) * kD + e;
    float a0 = 0.f, a1 = 0.f, a2 = 0.f, a3 = 0.f;
#pragma unroll
    for (int d = 0; d < 64; d += 4) {
        a0 = fmaf(a_s[d + 0], W[(size_t)(d + 0) * kD], a0);
        a1 = fmaf(a_s[d + 1], W[(size_t)(d + 1) * kD], a1);
        a2 = fmaf(a_s[d + 2], W[(size_t)(d + 2) * kD], a2);
        a3 = fmaf(a_s[d + 3], W[(size_t)(d + 3) * kD], a3);
    }
    g_qkp[(ks * kL + l) * kD + e] = (a0 + a1) + (a2 + a3);
}

// ============ K3: fused LN + logits + segment softmax accumulate ============
__global__ __launch_bounds__(256) void attn_k(const float* __restrict__ feats) {
    const int l = blockIdx.x, b = blockIdx.y;
    const int tid = threadIdx.x, wid = tid >> 5, lane = tid & 31;

    __shared__ float qk_s[kD];
    __shared__ float s_part[8][kD];
    __shared__ float den_part[8];

    for (int e = tid; e < kD; e += 256) {
        float s = 0.f;
#pragma unroll
        for (int ks = 0; ks < kKS; ks++) s += g_qkp[(ks * kL + l) * kD + e];
        qk_s[e] = s;
    }
    __syncthreads();

    float4 qk4[4];
    float qks = 0.f;
#pragma unroll
    for (int q = 0; q < 4; q++) {
        qk4[q] = *(const float4*)&qk_s[(lane + 32 * q) * 4];
        qks += sum4(qk4[q]);
    }
#pragma unroll
    for (int o = 16; o; o >>= 1) qks += __shfl_xor_sync(0xffffffffu, qks, o);

    const int nv = g_nvalid[b];
    int segsz = nv / kL; if (segsz < 1) segsz = 1;
    const int n_used = min(nv, kL * segsz);
    const int t0 = l * segsz;
    const int t1 = min(t0 + segsz, n_used);

    float4 sac[4];
#pragma unroll
    for (int q = 0; q < 4; q++) sac[q] = make_float4(0.f, 0.f, 0.f, 0.f);
    float dac = 0.f;

    for (int t = t0 + wid; t < t1; t += 8) {
        const int orig = g_order[b * kN + t];
        const float4* row = (const float4*)(feats + ((size_t)b * kN + orig) * kD);
        float4 v[4];
        float sm = 0.f, sq = 0.f, dt = 0.f;
#pragma unroll
        for (int q = 0; q < 4; q++) {
            v[q] = row[lane + 32 * q];
            sm += sum4(v[q]);
            sq += dot4(v[q], v[q]);
            dt += dot4(v[q], qk4[q]);
        }
#pragma unroll
        for (int o = 16; o; o >>= 1) {
            sm += __shfl_xor_sync(0xffffffffu, sm, o);
            sq += __shfl_xor_sync(0xffffffffu, sq, o);
            dt += __shfl_xor_sync(0xffffffffu, dt, o);
        }
        const float mu = sm * (1.0f / kD);
        const float var = sq * (1.0f / kD) - mu * mu;
        const float rstd = rsqrtf(var + 1e-5f);
        float logit = (dt - mu * qks) * rstd * kInvTemp;
        logit = fminf(5.0f, fmaxf(-5.0f, logit));
        const float w = expf(logit - 5.0f);
        const float wr = w * rstd;
        const float wm = wr * mu;
#pragma unroll
        for (int q = 0; q < 4; q++) {
            sac[q].x += wr * v[q].x - wm;
            sac[q].y += wr * v[q].y - wm;
            sac[q].z += wr * v[q].z - wm;
            sac[q].w += wr * v[q].w - wm;
        }
        dac += w;
    }

#pragma unroll
    for (int q = 0; q < 4; q++)
        *(float4*)&s_part[wid][(lane + 32 * q) * 4] = sac[q];
    if (lane == 0) den_part[wid] = dac;
    __syncthreads();

    float den = 0.f;
#pragma unroll
    for (int w = 0; w < 8; w++) den += den_part[w];

    const int m = b * kL + l;
    for (int e = tid; e < kD; e += 256) {
        float s = 0.f;
#pragma unroll
        for (int w = 0; w < 8; w++) s += s_part[w][e];
        g_U[(size_t)m * kD + e] = (den > 0.f) ? (s / den) : 0.f;
    }
    if (tid == 0) g_denom[m] = den;
}

// ============ K4/K5: split-K double-buffered SGEMM, partial slabs ===========
// C_part[kz][M,512] = A[M, kz*256 : kz*256+256] @ W[:, same]^T
// BM=32, BN=64, BK=16, 256 threads, 2x4 micro-tile, ping-pong smem,
// register prefetch, ONE __syncthreads per k-step.
// MODE 1: A = g_U (arg). MODE 2: A row = den>0 ? (g_P1[0]+g_P1[1]) : z row.
template <int MODE>
__global__ __launch_bounds__(256) void gemm_dbuf_k(const float* __restrict__ A,
                                                   const float* __restrict__ W,
                                                   const float* __restrict__ z,
                                                   float* __restrict__ Pout) {
    __shared__ float As[2][16][32];
    __shared__ float Bs[2][16][64];
    const int tid = threadIdx.x;
    const int m0 = blockIdx.y * 32, n0 = blockIdx.x * 64;
    const int kb = blockIdx.z * 256;
    const int tx = tid & 15, ty = tid >> 4;
    const int lr = tid >> 2, lk = (tid & 3) * 4;   // loader coords
    const bool aact = tid < 128;                    // A: 32 rows x 16 = 128 f4

    // resolve A row pointer (MODE 2 folds gemm1's reduce+replace epilogue)
    const float* arow = nullptr;
    bool sum2 = false;
    if (aact) {
        const int m = m0 + lr;
        if (MODE == 2) {
            if (g_denom[m] > 0.f) { arow = g_P1 + (size_t)m * kD; sum2 = true; }
            else                  { arow = z + (size_t)(m & (kL - 1)) * kD; }
        } else {
            arow = A + (size_t)m * kD;
        }
    }
    const float* wrow = W + (size_t)(n0 + lr) * kD + kb;

    float4 ra = make_float4(0.f, 0.f, 0.f, 0.f), rb;
    // prologue: tile 0 -> regs -> smem[0]
    if (aact) {
        ra = *(const float4*)(arow + kb + lk);
        if (MODE == 2 && sum2) {
            float4 q = *(const float4*)(arow + kSlab + kb + lk);
            ra.x += q.x; ra.y += q.y; ra.z += q.z; ra.w += q.w;
        }
    }
    rb = *(const float4*)(wrow + lk);
    if (aact) {
        As[0][lk + 0][lr] = ra.x; As[0][lk + 1][lr] = ra.y;
        As[0][lk + 2][lr] = ra.z; As[0][lk + 3][lr] = ra.w;
    }
    Bs[0][lk + 0][lr] = rb.x; Bs[0][lk + 1][lr] = rb.y;
    Bs[0][lk + 2][lr] = rb.z; Bs[0][lk + 3][lr] = rb.w;
    __syncthreads();

    float acc[2][4] = {};
    int cur = 0;
#pragma unroll 1
    for (int s = 0; s < 16; s++) {
        if (s < 15) {
            const int ko = kb + (s + 1) * 16;
            if (aact) {
                ra = *(const float4*)(arow + ko + lk);
                if (MODE == 2 && sum2) {
                    float4 q = *(const float4*)(arow + kSlab + ko + lk);
                    ra.x += q.x; ra.y += q.y; ra.z += q.z; ra.w += q.w;
                }
            }
            rb = *(const float4*)(wrow + (s + 1) * 16 + lk);
        }
#pragma unroll
        for (int k = 0; k < 16; k++) {
            float2 av = *(const float2*)&As[cur][k][ty * 2];
            float4 bv = *(const float4*)&Bs[cur][k][tx * 4];
            acc[0][0] += av.x * bv.x; acc[0][1] += av.x * bv.y;
            acc[0][2] += av.x * bv.z; acc[0][3] += av.x * bv.w;
            acc[1][0] += av.y * bv.x; acc[1][1] += av.y * bv.y;
            acc[1][2] += av.y * bv.z; acc[1][3] += av.y * bv.w;
        }
        if (s < 15) {
            const int nxt = cur ^ 1;
            if (aact) {
                As[nxt][lk + 0][lr] = ra.x; As[nxt][lk + 1][lr] = ra.y;
                As[nxt][lk + 2][lr] = ra.z; As[nxt][lk + 3][lr] = ra.w;
            }
            Bs[nxt][lk + 0][lr] = rb.x; Bs[nxt][lk + 1][lr] = rb.y;
            Bs[nxt][lk + 2][lr] = rb.z; Bs[nxt][lk + 3][lr] = rb.w;
            __syncthreads();
            cur = nxt;
        }
    }

    float* base = Pout + (size_t)blockIdx.z * kSlab;
#pragma unroll
    for (int i = 0; i < 2; i++) {
        const int m = m0 + ty * 2 + i;
        float4 v = make_float4(acc[i][0], acc[i][1], acc[i][2], acc[i][3]);
        *(float4*)(base + (size_t)m * kD + n0 + tx * 4) = v;
    }
}

// ============ K6: final reduce + bias + sample replacement ==================
__global__ __launch_bounds__(256) void fin_k(float* __restrict__ out,
                                             const float* __restrict__ z,
                                             const float* __restrict__ bo) {
    const int idx = blockIdx.x * 256 + threadIdx.x;  // float4 index, 0..65535
    const int m = idx >> 7;           // 128 float4 per row
    const int c4 = idx & 127;
    float4 v;
    if (g_nvalid[m >> 6] == 0) {
        v = ((const float4*)(z + (size_t)(m & (kL - 1)) * kD))[c4];
    } else {
        float4 p = ((const float4*)g_P2)[idx];
        float4 q = ((const float4*)g_P2)[idx + kSlab / 4];
        float4 b = ((const float4*)bo)[c4];
        v = make_float4(p.x + q.x + b.x, p.y + q.y + b.y,
                        p.z + q.z + b.z, p.w + q.w + b.w);
    }
    ((float4*)out)[idx] = v;
}

// ---------------------------------------------------------------------------
extern "C" void kernel_launch(void* const* d_in, const int* in_sizes, int n_in,
                              void* d_out, int out_size) {
    (void)in_sizes; (void)n_in; (void)out_size;
    const float* feats = (const float*)d_in[0];
    // d_in[1] = coords (unused by the reference output)
    const void*  mask  = d_in[2];
    const float* z     = (const float*)d_in[3];
    const float* Wq    = (const float*)d_in[4];
    const float* Wk    = (const float*)d_in[5];
    const float* Wv    = (const float*)d_in[6];
    const float* Wo    = (const float*)d_in[7];
    const float* bo    = (const float*)d_in[8];
    float* out = (float*)d_out;

    float *pU = nullptr, *pP1 = nullptr, *pP2 = nullptr;
    cudaGetSymbolAddress((void**)&pU, g_U);
    cudaGetSymbolAddress((void**)&pP1, g_P1);
    cudaGetSymbolAddress((void**)&pP2, g_P2);

    k1_order_qall<<<kB + (kL * kD) / 8, 256>>>(mask, z, Wq);
    qk_k<<<dim3(kL, kKS), 512>>>(Wk);
    attn_k<<<dim3(kL, kB), 256>>>(feats);
    gemm_dbuf_k<1><<<dim3(8, 16, 2), 256>>>(pU, Wv, z, pP1);
    gemm_dbuf_k<2><<<dim3(8, 16, 2), 256>>>(nullptr, Wo, z, pP2);
    fin_k<<<kM * kD / 4 / 256, 256>>>(out, z, bo);
}

// round 5
// speedup vs baseline: 1.7665x; 1.3284x over previous
#include <cuda_runtime.h>
#include <math.h>

namespace {
constexpr int kB = 8;
constexpr int kN = 4096;
constexpr int kD = 512;
constexpr int kL = 64;
constexpr int kKS = 8;                // split-k slices (qall/qk/big gemms)
constexpr int kM = kB * kL;           // 512 rows through the GEMMs
constexpr int kSlab = kM * kD;        // 262144 floats per partial slab
constexpr float kInvTemp = 0.044194173824159216f; // 1/sqrt(512)
}

// ---------------- scratch (device globals; no allocation allowed) ----------
__device__ int   g_order[kB * kN];
__device__ int   g_nvalid[kB];
__device__ float g_qallp[kKS * kL * kD];  // qall split-k partials
__device__ float g_qkp[kKS * kL * kD];    // qk split-k partials
__device__ float g_U[kM * kD];            // s_l / denom (0 if empty segment)
__device__ float g_denom[kM];
__device__ float g_P1[kKS * kSlab];       // gemm1 partials (U @ Wv^T)
__device__ float g_Zt[kSlab];             // reduced Zattn
__device__ float g_P2[kKS * kSlab];       // gemm2 partials (Zattn @ Wo^T)

__device__ __forceinline__ float dot4(float4 a, float4 b) {
    return a.x * b.x + a.y * b.y + a.z * b.z + a.w * b.w;
}
__device__ __forceinline__ float sum4(float4 a) { return a.x + a.y + a.z + a.w; }

__device__ __forceinline__ bool mask_at(const void* m, int idx, int kind) {
    if (kind == 1) return ((const int*)m)[idx] != 0;
    if (kind == 2) return ((const float*)m)[idx] != 0.0f;
    return ((const unsigned char*)m)[idx] != 0;
}

// ============ K1: blocks 0..7 build_order; blocks 8..71 qall GEMM ===========
// qall partials: qallp[kz][l][d] = z[l, kb:kb+64] @ Wq[d, kb:kb+64]^T
__global__ __launch_bounds__(256) void k1_order_qall(const void* __restrict__ mask,
                                                     const float* __restrict__ z,
                                                     const float* __restrict__ Wq) {
    const int tid = threadIdx.x;
    const int wid = tid >> 5, lane = tid & 31;

    __shared__ float Asm[64][68];
    __shared__ float Bsm[64][68];

    if (blockIdx.x < kB) {
        const int b = blockIdx.x;
        const unsigned* mw = (const unsigned*)mask;
        int iok = 1, fok = 1;
        for (int i = tid; i < 1024; i += 256) {
            unsigned v = mw[b * 1024 + i];
            iok &= (v <= 1u);
            fok &= (v == 0u || v == 0x3F800000u);
        }
        iok = __syncthreads_and(iok);
        fok = __syncthreads_and(fok);
        const int kind = iok ? 1 : (fok ? 2 : 0);

        const int base = tid * 16;
        bool v[16];
        int c = 0;
#pragma unroll
        for (int j = 0; j < 16; j++) {
            v[j] = !mask_at(mask, b * kN + base + j, kind);
            c += v[j] ? 1 : 0;
        }
        int inc = c;
#pragma unroll
        for (int o = 1; o < 32; o <<= 1) {
            int x = __shfl_up_sync(0xffffffffu, inc, o);
            if (lane >= o) inc += x;
        }
        __shared__ int wsum[8];
        if (lane == 31) wsum[wid] = inc;
        __syncthreads();
        __shared__ int woff[8];
        if (tid < 8) {
            int s = 0;
            for (int w = 0; w < 8; w++) { woff[w] = s; s += wsum[w]; }
            if (tid == 0) g_nvalid[b] = s;
        }
        __syncthreads();
        int pos = woff[wid] + inc - c;
#pragma unroll
        for (int j = 0; j < 16; j++) {
            if (v[j]) g_order[b * kN + pos++] = base + j;
        }
    } else {
        const int bid = blockIdx.x - kB;        // 0..63
        const int nt = bid & 7, kz = bid >> 3;
        const int kb = kz * 64;
        // A: z[l][kb+k], transposed into Asm[k][l]
        for (int jj = tid; jj < 1024; jj += 256) {
            const int l = jj >> 4, k4 = (jj & 15) * 4;
            float4 v = *(const float4*)(z + (size_t)l * kD + kb + k4);
            Asm[k4 + 0][l] = v.x; Asm[k4 + 1][l] = v.y;
            Asm[k4 + 2][l] = v.z; Asm[k4 + 3][l] = v.w;
        }
        // B: Wq[nt*64+d][kb+k], transposed into Bsm[k][d]
        for (int jj = tid; jj < 1024; jj += 256) {
            const int d = jj >> 4, k4 = (jj & 15) * 4;
            float4 v = *(const float4*)(Wq + (size_t)(nt * 64 + d) * kD + kb + k4);
            Bsm[k4 + 0][d] = v.x; Bsm[k4 + 1][d] = v.y;
            Bsm[k4 + 2][d] = v.z; Bsm[k4 + 3][d] = v.w;
        }
        __syncthreads();
        const int tx = tid & 15, ty = tid >> 4;
        float acc[4][4] = {};
#pragma unroll 4
        for (int k = 0; k < 64; k++) {
            float4 a = *(const float4*)&Asm[k][ty * 4];
            float4 b = *(const float4*)&Bsm[k][tx * 4];
            acc[0][0] += a.x * b.x; acc[0][1] += a.x * b.y; acc[0][2] += a.x * b.z; acc[0][3] += a.x * b.w;
            acc[1][0] += a.y * b.x; acc[1][1] += a.y * b.y; acc[1][2] += a.y * b.z; acc[1][3] += a.y * b.w;
            acc[2][0] += a.z * b.x; acc[2][1] += a.z * b.y; acc[2][2] += a.z * b.z; acc[2][3] += a.z * b.w;
            acc[3][0] += a.w * b.x; acc[3][1] += a.w * b.y; acc[3][2] += a.w * b.z; acc[3][3] += a.w * b.w;
        }
#pragma unroll
        for (int i = 0; i < 4; i++) {
            float4 v = make_float4(acc[i][0], acc[i][1], acc[i][2], acc[i][3]);
            *(float4*)&g_qallp[(size_t)kz * (kL * kD) + (size_t)(ty * 4 + i) * kD + nt * 64 + tx * 4] = v;
        }
    }
}

// ============ K2: qk GEMM — qkp[kz][l][e] = qall[l,kb:+64] @ Wk[kb:+64, e] ==
__global__ __launch_bounds__(256) void qk_gemm(const float* __restrict__ Wk) {
    const int tid = threadIdx.x;
    const int nt = blockIdx.x & 7, kz = blockIdx.x >> 3;
    const int kb = kz * 64;
    __shared__ float Asm[64][68];
    __shared__ float Bsm[64][68];
    // A: qall[l][kb+k] = sum of 8 partial slabs, transposed into Asm[k][l]
    for (int jj = tid; jj < 1024; jj += 256) {
        const int l = jj >> 4, k4 = (jj & 15) * 4;
        float4 v = make_float4(0.f, 0.f, 0.f, 0.f);
#pragma unroll
        for (int s = 0; s < kKS; s++) {
            float4 p = *(const float4*)&g_qallp[(size_t)s * (kL * kD) + (size_t)l * kD + kb + k4];
            v.x += p.x; v.y += p.y; v.z += p.z; v.w += p.w;
        }
        Asm[k4 + 0][l] = v.x; Asm[k4 + 1][l] = v.y;
        Asm[k4 + 2][l] = v.z; Asm[k4 + 3][l] = v.w;
    }
    // B: Wk[kb+k][nt*64+e] — natural layout into Bsm[k][e]
    for (int jj = tid; jj < 1024; jj += 256) {
        const int k = jj >> 4, e4 = (jj & 15) * 4;
        float4 v = *(const float4*)(Wk + (size_t)(kb + k) * kD + nt * 64 + e4);
        *(float4*)&Bsm[k][e4] = v;
    }
    __syncthreads();
    const int tx = tid & 15, ty = tid >> 4;
    float acc[4][4] = {};
#pragma unroll 4
    for (int k = 0; k < 64; k++) {
        float4 a = *(const float4*)&Asm[k][ty * 4];
        float4 b = *(const float4*)&Bsm[k][tx * 4];
        acc[0][0] += a.x * b.x; acc[0][1] += a.x * b.y; acc[0][2] += a.x * b.z; acc[0][3] += a.x * b.w;
        acc[1][0] += a.y * b.x; acc[1][1] += a.y * b.y; acc[1][2] += a.y * b.z; acc[1][3] += a.y * b.w;
        acc[2][0] += a.z * b.x; acc[2][1] += a.z * b.y; acc[2][2] += a.z * b.z; acc[2][3] += a.z * b.w;
        acc[3][0] += a.w * b.x; acc[3][1] += a.w * b.y; acc[3][2] += a.w * b.z; acc[3][3] += a.w * b.w;
    }
#pragma unroll
    for (int i = 0; i < 4; i++) {
        float4 v = make_float4(acc[i][0], acc[i][1], acc[i][2], acc[i][3]);
        *(float4*)&g_qkp[(size_t)(kz * kL + ty * 4 + i) * kD + nt * 64 + tx * 4] = v;
    }
}

// ============ K3: fused LN + logits + segment softmax accumulate ============
__global__ __launch_bounds__(256) void attn_k(const float* __restrict__ feats) {
    const int l = blockIdx.x, b = blockIdx.y;
    const int tid = threadIdx.x, wid = tid >> 5, lane = tid & 31;

    __shared__ float qk_s[kD];
    __shared__ float s_part[8][kD];
    __shared__ float den_part[8];

    for (int e = tid; e < kD; e += 256) {
        float s = 0.f;
#pragma unroll
        for (int ks = 0; ks < kKS; ks++) s += g_qkp[(size_t)(ks * kL + l) * kD + e];
        qk_s[e] = s;
    }
    __syncthreads();

    float4 qk4[4];
    float qks = 0.f;
#pragma unroll
    for (int q = 0; q < 4; q++) {
        qk4[q] = *(const float4*)&qk_s[(lane + 32 * q) * 4];
        qks += sum4(qk4[q]);
    }
#pragma unroll
    for (int o = 16; o; o >>= 1) qks += __shfl_xor_sync(0xffffffffu, qks, o);

    const int nv = g_nvalid[b];
    int segsz = nv / kL; if (segsz < 1) segsz = 1;
    const int n_used = min(nv, kL * segsz);
    const int t0 = l * segsz;
    const int t1 = min(t0 + segsz, n_used);

    float4 sac[4];
#pragma unroll
    for (int q = 0; q < 4; q++) sac[q] = make_float4(0.f, 0.f, 0.f, 0.f);
    float dac = 0.f;

    for (int t = t0 + wid; t < t1; t += 8) {
        const int orig = g_order[b * kN + t];
        const float4* row = (const float4*)(feats + ((size_t)b * kN + orig) * kD);
        float4 v[4];
        float sm = 0.f, sq = 0.f, dt = 0.f;
#pragma unroll
        for (int q = 0; q < 4; q++) {
            v[q] = row[lane + 32 * q];
            sm += sum4(v[q]);
            sq += dot4(v[q], v[q]);
            dt += dot4(v[q], qk4[q]);
        }
#pragma unroll
        for (int o = 16; o; o >>= 1) {
            sm += __shfl_xor_sync(0xffffffffu, sm, o);
            sq += __shfl_xor_sync(0xffffffffu, sq, o);
            dt += __shfl_xor_sync(0xffffffffu, dt, o);
        }
        const float mu = sm * (1.0f / kD);
        const float var = sq * (1.0f / kD) - mu * mu;
        const float rstd = rsqrtf(var + 1e-5f);
        float logit = (dt - mu * qks) * rstd * kInvTemp;
        logit = fminf(5.0f, fmaxf(-5.0f, logit));
        const float w = expf(logit - 5.0f);
        const float wr = w * rstd;
        const float wm = wr * mu;
#pragma unroll
        for (int q = 0; q < 4; q++) {
            sac[q].x += wr * v[q].x - wm;
            sac[q].y += wr * v[q].y - wm;
            sac[q].z += wr * v[q].z - wm;
            sac[q].w += wr * v[q].w - wm;
        }
        dac += w;
    }

#pragma unroll
    for (int q = 0; q < 4; q++)
        *(float4*)&s_part[wid][(lane + 32 * q) * 4] = sac[q];
    if (lane == 0) den_part[wid] = dac;
    __syncthreads();

    float den = 0.f;
#pragma unroll
    for (int w = 0; w < 8; w++) den += den_part[w];

    const int m = b * kL + l;
    for (int e = tid; e < kD; e += 256) {
        float s = 0.f;
#pragma unroll
        for (int w = 0; w < 8; w++) s += s_part[w][e];
        g_U[(size_t)m * kD + e] = (den > 0.f) ? (s / den) : 0.f;
    }
    if (tid == 0) g_denom[m] = den;
}

// ============ K4/K6: big SGEMM — BM=128, BN=64, kz=8, 8x4 micro =============
// Pout[kz][m][n] = A[m, kb:kb+64] @ W[n, kb:kb+64]^T, double-buffered smem.
__global__ __launch_bounds__(256) void gemm_big(const float* __restrict__ A,
                                                const float* __restrict__ W,
                                                float* __restrict__ Pout) {
    __shared__ float As[2][16][132];
    __shared__ float Bs[2][16][68];
    const int tid = threadIdx.x;
    const int n0 = blockIdx.x * 64, m0 = blockIdx.y * 128, kb = blockIdx.z * 64;
    const int tx = tid & 15, ty = tid >> 4;

    // loaders: A two float4 per step (rows tid>>2 and 64+(tid>>2)); B one.
    const int ak4 = (tid & 3) * 4;
    const int am0 = tid >> 2, am1 = 64 + (tid >> 2);
    const float* arow0 = A + (size_t)(m0 + am0) * kD + kb + ak4;
    const float* arow1 = A + (size_t)(m0 + am1) * kD + kb + ak4;
    const float* brow  = W + (size_t)(n0 + (tid >> 2)) * kD + kb + ak4;

    float4 ra0 = *(const float4*)arow0;
    float4 ra1 = *(const float4*)arow1;
    float4 rb  = *(const float4*)brow;
#pragma unroll
    for (int c = 0; c < 4; c++) {
        As[0][ak4 + c][am0] = ((const float*)&ra0)[c];
        As[0][ak4 + c][am1] = ((const float*)&ra1)[c];
        Bs[0][ak4 + c][tid >> 2] = ((const float*)&rb)[c];
    }
    __syncthreads();

    float acc[8][4] = {};
    int cur = 0;
#pragma unroll 1
    for (int s = 0; s < 4; s++) {
        if (s < 3) {
            ra0 = *(const float4*)(arow0 + (s + 1) * 16);
            ra1 = *(const float4*)(arow1 + (s + 1) * 16);
            rb  = *(const float4*)(brow + (s + 1) * 16);
        }
#pragma unroll
        for (int k = 0; k < 16; k++) {
            float4 a0 = *(const float4*)&As[cur][k][ty * 8];
            float4 a1 = *(const float4*)&As[cur][k][ty * 8 + 4];
            float4 bv = *(const float4*)&Bs[cur][k][tx * 4];
            const float* ap = (const float*)&a0;
            const float* aq = (const float*)&a1;
#pragma unroll
            for (int i = 0; i < 4; i++) {
                acc[i][0] += ap[i] * bv.x; acc[i][1] += ap[i] * bv.y;
                acc[i][2] += ap[i] * bv.z; acc[i][3] += ap[i] * bv.w;
                acc[i + 4][0] += aq[i] * bv.x; acc[i + 4][1] += aq[i] * bv.y;
                acc[i + 4][2] += aq[i] * bv.z; acc[i + 4][3] += aq[i] * bv.w;
            }
        }
        if (s < 3) {
            const int nxt = cur ^ 1;
#pragma unroll
            for (int c = 0; c < 4; c++) {
                As[nxt][ak4 + c][am0] = ((const float*)&ra0)[c];
                As[nxt][ak4 + c][am1] = ((const float*)&ra1)[c];
                Bs[nxt][ak4 + c][tid >> 2] = ((const float*)&rb)[c];
            }
            __syncthreads();
            cur = nxt;
        }
    }

    float* base = Pout + (size_t)blockIdx.z * kSlab;
#pragma unroll
    for (int i = 0; i < 8; i++) {
        const int m = m0 + ty * 8 + i;
        float4 v = make_float4(acc[i][0], acc[i][1], acc[i][2], acc[i][3]);
        *(float4*)(base + (size_t)m * kD + n0 + tx * 4) = v;
    }
}

// ============ K5: reduce P1 -> Zattn (+ empty-segment replacement) ==========
__global__ __launch_bounds__(256) void reduce1_k(const float* __restrict__ z) {
    const int idx = blockIdx.x * 256 + threadIdx.x;  // float4 index
    const int m = idx >> 7, c4 = idx & 127;
    float4 v;
    if (g_denom[m] > 0.f) {
        v = make_float4(0.f, 0.f, 0.f, 0.f);
#pragma unroll
        for (int s = 0; s < kKS; s++) {
            float4 p = ((const float4*)g_P1)[(size_t)s * (kSlab / 4) + idx];
            v.x += p.x; v.y += p.y; v.z += p.z; v.w += p.w;
        }
    } else {
        v = ((const float4*)(z + (size_t)(m & (kL - 1)) * kD))[c4];
    }
    ((float4*)g_Zt)[idx] = v;
}

// ============ K7: final reduce + bias + sample replacement ==================
__global__ __launch_bounds__(256) void fin_k(float* __restrict__ out,
                                             const float* __restrict__ z,
                                             const float* __restrict__ bo) {
    const int idx = blockIdx.x * 256 + threadIdx.x;  // float4 index
    const int m = idx >> 7, c4 = idx & 127;
    float4 v;
    if (g_nvalid[m >> 6] == 0) {
        v = ((const float4*)(z + (size_t)(m & (kL - 1)) * kD))[c4];
    } else {
        float4 b = ((const float4*)bo)[c4];
        v = b;
#pragma unroll
        for (int s = 0; s < kKS; s++) {
            float4 p = ((const float4*)g_P2)[(size_t)s * (kSlab / 4) + idx];
            v.x += p.x; v.y += p.y; v.z += p.z; v.w += p.w;
        }
    }
    ((float4*)out)[idx] = v;
}

// ---------------------------------------------------------------------------
extern "C" void kernel_launch(void* const* d_in, const int* in_sizes, int n_in,
                              void* d_out, int out_size) {
    (void)in_sizes; (void)n_in; (void)out_size;
    const float* feats = (const float*)d_in[0];
    // d_in[1] = coords (unused by the reference output)
    const void*  mask  = d_in[2];
    const float* z     = (const float*)d_in[3];
    const float* Wq    = (const float*)d_in[4];
    const float* Wk    = (const float*)d_in[5];
    const float* Wv    = (const float*)d_in[6];
    const float* Wo    = (const float*)d_in[7];
    const float* bo    = (const float*)d_in[8];
    float* out = (float*)d_out;

    float *pU = nullptr, *pZt = nullptr, *pP1 = nullptr, *pP2 = nullptr;
    cudaGetSymbolAddress((void**)&pU, g_U);
    cudaGetSymbolAddress((void**)&pZt, g_Zt);
    cudaGetSymbolAddress((void**)&pP1, g_P1);
    cudaGetSymbolAddress((void**)&pP2, g_P2);

    k1_order_qall<<<kB + 64, 256>>>(mask, z, Wq);
    qk_gemm<<<64, 256>>>(Wk);
    attn_k<<<dim3(kL, kB), 256>>>(feats);
    gemm_big<<<dim3(8, 4, kKS), 256>>>(pU, Wv, pP1);
    reduce1_k<<<kSlab / 4 / 256, 256>>>(z);
    gemm_big<<<dim3(8, 4, kKS), 256>>>(pZt, Wo, pP2);
    fin_k<<<kSlab / 4 / 256, 256>>>(out, z, bo);
}